// round 8
// baseline (speedup 1.0000x reference)
#include <cuda_runtime.h>
#include <cstdint>

// Problem constants
#define BATCH 16
#define CH    256
#define HH    64
#define WW    64
#define TROWS 66                 // 64 rows + top/bottom halo
#define ROWF  72                 // smem row stride (floats); data at cols 4..67
#define NBUF  2
#define BUFF  (TROWS * ROWF)
#define BUFB  (BUFF * 4)         // 19008 bytes per buffer

// Pair-group schedule: group g covers couts {2g, 2g+1}, g = 0..127.
// Nesting (A(2g+1) ⊆ A(2g)) means one plane-load set serves both couts.
// Split: g0->16 chunks, g1->8, g2->4, g3->2, g4..g127 -> 1.
#define NCHUNK 30                 // 16+8+4+2 split chunks
#define GRID_X (NCHUNK + 124)     // 154 schedule entries
#define NPLANES (NCHUNK * 2)      // 60 partial planes

// ---------------------------------------------------------------------------
// Scratch (device globals — no runtime allocation allowed)
// ---------------------------------------------------------------------------
__device__ float g_scale[CH * CH];
__device__ int   g_cin  [128 * CH];          // per-group compacted cin list
__device__ float g_wp   [128 * CH * 24];     // per (group,slot): w_lo[9],pad,pad,flag, w_hi[9],pad x3
__device__ int   g_count[128];
__device__ float g_part [NPLANES * BATCH * HH * WW];   // ~15.7 MB partials

// ---------------------------------------------------------------------------
// cp.async helpers
// ---------------------------------------------------------------------------
__device__ __forceinline__ void cp_async16(uint32_t saddr, const float* gptr, int src_size) {
    asm volatile("cp.async.ca.shared.global [%0], [%1], 16, %2;\n"
                 :: "r"(saddr), "l"(gptr), "r"(src_size));
}
__device__ __forceinline__ void cp_commit() {
    asm volatile("cp.async.commit_group;\n" ::);
}
template <int N> __device__ __forceinline__ void cp_wait() {
    asm volatile("cp.async.wait_group %0;\n" :: "n"(N));
}

// ---------------------------------------------------------------------------
// K1a: parallel cumprod (Kogge-Stone, 8 steps). Block = cin, thread = cout.
// ---------------------------------------------------------------------------
__global__ void scan_kernel(const float* __restrict__ weight) {
    int cin = blockIdx.x;
    int co  = threadIdx.x;
    __shared__ float sh[CH];
    sh[co] = (co == 0) ? 1.0f : fmaxf(weight[co * CH + cin], 0.0f);
    __syncthreads();
    #pragma unroll
    for (int off = 1; off < CH; off <<= 1) {
        float t = (co >= off) ? sh[co - off] : 1.0f;
        __syncthreads();
        sh[co] *= t;
        __syncthreads();
    }
    g_scale[co * CH + cin] = sh[co];
}

// ---------------------------------------------------------------------------
// K1b: pair-group compaction.  Block = group g (128), thread = cin.
// Active set = A(2g) (superset of A(2g+1) by nesting).  Deterministic
// ballot/popc compaction.  Stores both couts' scaled weights per slot;
// wd[11] = 1.0 iff the hi cout is active for this cin (else hi weights = 0).
// ---------------------------------------------------------------------------
__global__ void pair_compact_kernel(const float* __restrict__ conv_w) {
    int g   = blockIdx.x;
    int cin = threadIdx.x;
    int co_lo = 2 * g, co_hi = 2 * g + 1;
    float sc_lo = g_scale[co_lo * CH + cin];
    float sc_hi = g_scale[co_hi * CH + cin];
    bool active = (sc_lo != 0.0f);
    unsigned mask = __ballot_sync(0xffffffffu, active);
    int lane = cin & 31, warp = cin >> 5;
    __shared__ int wcnt[8];
    if (lane == 0) wcnt[warp] = __popc(mask);
    __syncthreads();
    int base = 0;
    #pragma unroll
    for (int i = 0; i < 8; i++)
        if (i < warp) base += wcnt[i];
    if (active) {
        int slot = base + __popc(mask & ((1u << lane) - 1u));
        g_cin[g * CH + slot] = cin;
        const float* wl = conv_w + (size_t)(co_lo * CH + cin) * 9;
        const float* wh = conv_w + (size_t)(co_hi * CH + cin) * 9;
        float* wd = g_wp + (size_t)(g * CH + slot) * 24;
        #pragma unroll
        for (int k = 0; k < 9; k++) wd[k] = wl[k] * sc_lo;
        wd[9] = 0.0f; wd[10] = 0.0f;
        wd[11] = (sc_hi != 0.0f) ? 1.0f : 0.0f;
        #pragma unroll
        for (int k = 0; k < 9; k++) wd[12 + k] = wh[k] * sc_hi;
        wd[21] = 0.0f; wd[22] = 0.0f; wd[23] = 0.0f;
    }
    if (cin == 0) {
        int t = 0;
        #pragma unroll
        for (int i = 0; i < 8; i++) t += wcnt[i];
        g_count[g] = t;
    }
}

// ---------------------------------------------------------------------------
// 3x3 apply: one smem sweep, one cout's weights into one 4x4 accumulator.
// ---------------------------------------------------------------------------
__device__ __forceinline__ void apply_tile(float (&acc)[4][4], const float* wk,
                                           const float* tb, int rg, int cg) {
    #pragma unroll
    for (int r = 0; r < 6; r++) {
        const float* rowp = tb + (4 * rg + r) * ROWF + 4 * cg;
        float4 m = *reinterpret_cast<const float4*>(rowp + 4);
        float vv[6] = {rowp[3], m.x, m.y, m.z, m.w, rowp[8]};
        #pragma unroll
        for (int dy = 0; dy < 3; dy++) {
            int orow = r - dy;
            if (orow >= 0 && orow < 4) {
                #pragma unroll
                for (int c = 0; c < 4; c++) {
                    acc[orow][c] = fmaf(wk[dy * 3 + 0], vv[c + 0], acc[orow][c]);
                    acc[orow][c] = fmaf(wk[dy * 3 + 1], vv[c + 1], acc[orow][c]);
                    acc[orow][c] = fmaf(wk[dy * 3 + 2], vv[c + 2], acc[orow][c]);
                }
            }
        }
    }
}

// ---------------------------------------------------------------------------
// K2: whole-plane 3x3 conv, one pair-group chunk per block.
// grid = (154 entries, 16 batch), 256 threads, 4x4 micro-tile per thread,
// 2-buffer cp.async ring.  Each plane load feeds BOTH couts of the pair.
// ---------------------------------------------------------------------------
__global__ __launch_bounds__(256) void conv_kernel(const float* __restrict__ in,
                                                   const float* __restrict__ bias,
                                                   float* __restrict__ out) {
    int y   = blockIdx.x;
    int b   = blockIdx.y;
    int tid = threadIdx.x;
    int cg  = tid & 15;
    int rg  = tid >> 4;

    // Schedule entry -> (group, nchunks, chunk, partial slot)
    int g, nck, ch, pslot;
    if      (y < 16) { g = 0;      nck = 16; ch = y;      pslot = y;  }
    else if (y < 24) { g = 1;      nck = 8;  ch = y - 16; pslot = y;  }
    else if (y < 28) { g = 2;      nck = 4;  ch = y - 24; pslot = y;  }
    else if (y < 30) { g = 3;      nck = 2;  ch = y - 28; pslot = y;  }
    else             { g = y - 26; nck = 1;  ch = 0;      pslot = -1; }

    int cnt = g_count[g];
    int lo  = ch * cnt / nck;
    int n   = (ch + 1) * cnt / nck - lo;
    int gbase = g * CH;

    extern __shared__ __align__(16) float smem[];   // [NBUF][TROWS][ROWF]
    uint32_t smem_u32 = (uint32_t)__cvta_generic_to_shared(smem);

    float acc0[4][4] = {};
    float acc1[4][4] = {};

    if (n > 0) {
        // Permanent zero halo columns (float cols 3 and 68) in both buffers.
        for (int i = tid; i < NBUF * TROWS * 2; i += 256) {
            int buf = i / (TROWS * 2);
            int rem = i - buf * (TROWS * 2);
            int r = rem >> 1;
            int c = (rem & 1) ? 68 : 3;
            smem[buf * BUFF + r * ROWF + c] = 0.0f;
        }

        auto issue = [&](int s) {
            const float* plane = in + (((size_t)b * CH + g_cin[gbase + lo + s]) << 12);
            uint32_t bo = (uint32_t)(s & 1) * BUFB;
            #pragma unroll
            for (int i = 0; i < 5; i++) {
                int idx = tid + 256 * i;
                if (i < 4 || tid < 32) {
                    int r = idx >> 4, c4 = idx & 15;
                    int gy = r - 1;
                    int sz = (gy >= 0 && gy < HH) ? 16 : 0;
                    cp_async16(smem_u32 + bo + (uint32_t)((r * ROWF + 4 + 4 * c4) * 4),
                               plane + gy * WW + c4 * 4, sz);
                }
            }
            cp_commit();
        };

        issue(0);

        for (int s = 0; s < n; ++s) {
            cp_wait<0>();
            __syncthreads();              // slot s visible; other buffer free

            if (s + 1 < n) issue(s + 1);

            const float4* wp = reinterpret_cast<const float4*>(g_wp + (size_t)(gbase + lo + s) * 24);
            float4 a0 = __ldg(wp);
            float4 a1 = __ldg(wp + 1);
            float4 a2 = __ldg(wp + 2);     // a2.y/a2.z pad, a2.w = hi-active flag
            const float* tb = smem + (s & 1) * BUFF;

            {
                float wk[9] = {a0.x, a0.y, a0.z, a0.w, a1.x, a1.y, a1.z, a1.w, a2.x};
                apply_tile(acc0, wk, tb, rg, cg);
            }
            if (a2.w != 0.0f) {            // uniform branch (same slot block-wide)
                float4 b0 = __ldg(wp + 3);
                float4 b1 = __ldg(wp + 4);
                float4 b2 = __ldg(wp + 5);
                float wk[9] = {b0.x, b0.y, b0.z, b0.w, b1.x, b1.y, b1.z, b1.w, b2.x};
                apply_tile(acc1, wk, tb, rg, cg);
            }
        }
    }

    if (pslot < 0) {
        float bv0 = __ldg(bias + 2 * g);
        float bv1 = __ldg(bias + 2 * g + 1);
        float4* o0 = reinterpret_cast<float4*>(out) + (((size_t)b * CH + 2 * g) << 10);
        float4* o1 = reinterpret_cast<float4*>(out) + (((size_t)b * CH + 2 * g + 1) << 10);
        #pragma unroll
        for (int r = 0; r < 4; r++) {
            int idx = ((4 * rg + r) << 4) + cg;
            o0[idx] = make_float4(acc0[r][0] + bv0, acc0[r][1] + bv0, acc0[r][2] + bv0, acc0[r][3] + bv0);
            o1[idx] = make_float4(acc1[r][0] + bv1, acc1[r][1] + bv1, acc1[r][2] + bv1, acc1[r][3] + bv1);
        }
    } else {
        // Unconditional partial writes (replay-safe even when n == 0).
        float4* p0 = reinterpret_cast<float4*>(g_part) + ((size_t)(pslot * 2) * BATCH + b) * 1024;
        float4* p1 = reinterpret_cast<float4*>(g_part) + ((size_t)(pslot * 2 + 1) * BATCH + b) * 1024;
        #pragma unroll
        for (int r = 0; r < 4; r++) {
            int idx = ((4 * rg + r) << 4) + cg;
            p0[idx] = make_float4(acc0[r][0], acc0[r][1], acc0[r][2], acc0[r][3]);
            p1[idx] = make_float4(acc1[r][0], acc1[r][1], acc1[r][2], acc1[r][3]);
        }
    }
}

// ---------------------------------------------------------------------------
// K3: reduce partials for couts 0..7 (the split pair-groups g0..g3), + bias.
// grid = 8 couts x 16 b x 8 px-chunks = 1024 blocks, 128 threads,
// 1 float4/thread, unrolled guarded 16-deep k-loop.
// ---------------------------------------------------------------------------
__global__ __launch_bounds__(128) void reduce_kernel(const float* __restrict__ bias,
                                                     float* __restrict__ out) {
    const int nck_t[8]   = {16, 16, 8, 8, 4, 4, 2, 2};
    const int pbase_t[8] = {0, 0, 16, 16, 24, 24, 28, 28};
    int blk = blockIdx.x;
    int co  = blk >> 7;            // 0..7
    int rem = blk & 127;
    int b   = rem >> 3;            // 0..15
    int q   = rem & 7;             // px chunk
    int nck = nck_t[co], pbase = pbase_t[co], which = co & 1;

    int v4 = q * 128 + threadIdx.x;          // 0..1023 float4 index
    float bv = __ldg(bias + co);
    float4 acc = make_float4(bv, bv, bv, bv);

    const float4* part4 = reinterpret_cast<const float4*>(g_part);
    size_t base = ((size_t)(pbase * 2 + which) * BATCH + b) * 1024 + v4;
    const size_t stride = (size_t)2 * BATCH * 1024;     // next chunk's plane

    #pragma unroll
    for (int k = 0; k < 16; ++k) {
        if (k < nck) {
            float4 p = part4[base + (size_t)k * stride];
            acc.x += p.x; acc.y += p.y; acc.z += p.z; acc.w += p.w;
        }
    }

    reinterpret_cast<float4*>(out)[(((size_t)b * CH + co) << 10) + v4] = acc;
}

// ---------------------------------------------------------------------------
// Entry point. Inputs (metadata order): input, conv_w, conv_b, weight.
// ---------------------------------------------------------------------------
extern "C" void kernel_launch(void* const* d_in, const int* in_sizes, int n_in,
                              void* d_out, int out_size) {
    (void)in_sizes; (void)n_in; (void)out_size;
    const float* input  = (const float*)d_in[0];
    const float* conv_w = (const float*)d_in[1];
    const float* conv_b = (const float*)d_in[2];
    const float* weight = (const float*)d_in[3];
    float* out = (float*)d_out;

    const int dyn_smem = NBUF * BUFB;   // 38016 bytes
    cudaFuncSetAttribute(conv_kernel, cudaFuncAttributeMaxDynamicSharedMemorySize, dyn_smem);

    scan_kernel<<<CH, CH>>>(weight);
    pair_compact_kernel<<<128, CH>>>(conv_w);
    dim3 grid(GRID_X, BATCH);
    conv_kernel<<<grid, 256, dyn_smem>>>(input, conv_b, out);
    reduce_kernel<<<8 * BATCH * 8, 128>>>(conv_b, out);
}